// round 15
// baseline (speedup 1.0000x reference)
#include <cuda_runtime.h>
#include <math.h>

// Fixed problem shapes
#define BS     4
#define C_     64
#define H_     64
#define W_     64
#define HW     4096     // H*W
#define NPTS   4096
#define M_TOT  (BS*HW)  // 16384

#define CELL   4
#define GRIDC  16       // 64/CELL
#define NCELL  (GRIDC*GRIDC)
#define CAP    64       // max points per cell (mean 16; +12 sigma unreachable)
#define CAND_CAP 640    // >= 9*CAP impossible; actual total ~144

#define LRELU_SLOPE 0.1f

// ---------------- device scratch (no allocations allowed) ----------------
__device__ float  g_f3t[BS * NPTS * C_];          // feat_3d transposed [b][n][c] (4 MB)
__device__ float4 g_cellpts[BS * NCELL * CAP];    // per-cell point arrays (1 MB)
__device__ int    g_ccount[BS * NCELL];           // zero at load; reset by K2's last block
__device__ int    g_done;                         // K2 completion counter (zero at load)

// ---------------- K1: bin (blocks 0..63) + transpose (blocks 64..1087) ----------------
__global__ void bin_transpose(const float* __restrict__ uv,
                              const float* __restrict__ f3) {
    __shared__ float tile[32][33];
    int tid = threadIdx.x;            // 256

    if (blockIdx.x < 64) {
        // ---- direct scatter binning: 1 point/thread ----
        int b     = blockIdx.x >> 4;
        int slice = blockIdx.x & 15;
        int n     = slice * 256 + tid;
        const float* uvb = uv + (size_t)b * 2 * NPTS;
        float u = uvb[n], v = uvb[NPTS + n];
        int cx = (int)(u * 0.25f);    // exact power-of-2 scale -> floor
        int cy = (int)(v * 0.25f);
        int c  = b * NCELL + cy * GRIDC + cx;
        int pos = atomicAdd(&g_ccount[c], 1);
        if (pos < CAP)
            g_cellpts[(size_t)c * CAP + pos] =
                make_float4(u, v,
                            __fadd_rn(__fmul_rn(u, u), __fmul_rn(v, v)),
                            __int_as_float(n));
        return;
    }

    // ---- transpose: 32x32 tile, float4 both ways ----
    int tix = blockIdx.x - 64;        // 0..1023
    int b   = tix >> 8;
    int rem = tix & 255;
    int c0  = (rem >> 7) * 32;
    int n0  = (rem & 127) * 32;
    const float* src = f3 + ((size_t)(b * C_ + c0)) * NPTS + n0;
    {
        int row  = tid >> 3;          // c within tile
        int col4 = tid & 7;           // float4 slot along n
        float4 v = *(const float4*)(src + row * NPTS + col4 * 4);
        tile[row][col4 * 4 + 0] = v.x;
        tile[row][col4 * 4 + 1] = v.y;
        tile[row][col4 * 4 + 2] = v.z;
        tile[row][col4 * 4 + 3] = v.w;
    }
    __syncthreads();
    float* dst = g_f3t + ((size_t)(b * NPTS + n0)) * C_ + c0;
    {
        int n    = tid >> 3;          // n within tile
        int col4 = tid & 7;           // float4 slot along c
        float4 v = make_float4(tile[col4 * 4 + 0][n],
                               tile[col4 * 4 + 1][n],
                               tile[col4 * 4 + 2][n],
                               tile[col4 * 4 + 3][n]);
        *(float4*)(dst + n * C_ + col4 * 4) = v;
    }
}

// ---------------- K2: fused per-cell knn + score MLP + out matvec ----------------
// 1024 blocks x 128 threads; block = (b, cell) = 16 queries.
// Phase 1: validated per-cell knn (8 threads/query, width-8 shfl merge) -> sKnn.
//   d rounding identical: cross = fma(fy, v, rn(fx*u)); d = rn(rn(g2+u2) - rn(2*cross))
//   Selection: (d, idx) lexicographic -> order-independent, matches top_k ties.
// Phase 2: validated score (4 warps x 4 queries, shfl z-path) -> sF (per-channel final).
// Phase 3: per-query 64x64 matvec, c-ascending fma (validated GEMM order) + bias + lrelu.
// Phase 4: float4 writeout per (o, pixel row).
// Last-finishing block resets g_ccount for the next graph replay.
#define INS(dv, iv)                                                     \
    if ((dv) < d2 || ((dv) == d2 && (iv) < i2)) {                       \
        if ((dv) < d1 || ((dv) == d1 && (iv) < i1)) {                   \
            d2 = d1; i2 = i1;                                           \
            if ((dv) < d0 || ((dv) == d0 && (iv) < i0)) {               \
                d1 = d0; i1 = i0; d0 = (dv); i0 = (iv);                 \
            } else { d1 = (dv); i1 = (iv); }                            \
        } else { d2 = (dv); i2 = (iv); }                                \
    }

__global__ void fused_cell(const float* __restrict__ uv,
                           const float* __restrict__ w1, const float* __restrict__ b1,
                           const float* __restrict__ w2, const float* __restrict__ b2,
                           const float* __restrict__ w_out,
                           const float* __restrict__ b_out,
                           float* __restrict__ out) {
    __shared__ float4 cand[CAND_CAP];         // 10.2 KB
    __shared__ float  Wt[64 * 64];            // 16 KB, [c][o]
    __shared__ float  sF[16 * 65];            // final[q][c], padded
    __shared__ float  sOut[16 * 68];          // out[q][o], padded
    __shared__ int    sKnn[16 * 3];
    __shared__ int    sIsLast;

    int tid  = threadIdx.x;           // 128
    int lane = tid & 31;
    int wid  = tid >> 5;              // 4 warps
    int b    = blockIdx.x >> 8;
    int cell = blockIdx.x & 255;
    int cx = cell & (GRIDC - 1), cy = cell >> 4;

    // ---- stage Wt (independent of knn) ----
    for (int idx = tid; idx < 4096; idx += 128) {
        int o = idx >> 6, c = idx & 63;
        Wt[c * 64 + o] = w_out[idx];
    }

    // ---- Phase 1: knn (validated per-cell) ----
    int xlo = max(cx - 1, 0), xhi = min(cx + 1, GRIDC - 1);
    int ylo = max(cy - 1, 0), yhi = min(cy + 1, GRIDC - 1);
    int cbase[9], ccnt[9], coff[9], ncl = 0, total = 0;
    for (int y = ylo; y <= yhi; y++)
        for (int x = xlo; x <= xhi; x++) {
            int c = b * NCELL + y * GRIDC + x;
            int n = __ldg(&g_ccount[c]);
            if (n > CAP) n = CAP;
            cbase[ncl] = c * CAP; ccnt[ncl] = n; coff[ncl] = total;
            total += n; ncl++;
        }
    for (int k = 0; k < ncl; k++)
        for (int i = tid; i < ccnt[k]; i += 128)
            cand[coff[k] + i] = g_cellpts[(size_t)cbase[k] + i];
    __syncthreads();

    {
        int g   = tid >> 3;               // 0..15
        int sub = tid & 7;
        int px = cx * CELL + (g & 3);
        int py = cy * CELL + (g >> 2);
        float fx = (float)px, fy = (float)py;
        float g2 = fx * fx + fy * fy;     // exact (small ints)

        float d0 = 3.4e38f, d1 = 3.4e38f, d2 = 3.4e38f;
        int   i0 = 0x7fffffff, i1 = 0x7fffffff, i2 = 0x7fffffff;

        for (int p = sub; p < total; p += 8) {
            float4 P = cand[p];
            float cross = __fmaf_rn(fy, P.y, __fmul_rn(fx, P.x));
            float d = __fsub_rn(__fadd_rn(g2, P.z), __fadd_rn(cross, cross));
            int idx = __float_as_int(P.w);
            INS(d, idx);
        }

        #pragma unroll
        for (int off = 4; off > 0; off >>= 1) {
            float e0 = __shfl_down_sync(0xffffffffu, d0, off, 8);
            int   j0 = __shfl_down_sync(0xffffffffu, i0, off, 8);
            float e1 = __shfl_down_sync(0xffffffffu, d1, off, 8);
            int   j1 = __shfl_down_sync(0xffffffffu, i1, off, 8);
            float e2 = __shfl_down_sync(0xffffffffu, d2, off, 8);
            int   j2 = __shfl_down_sync(0xffffffffu, i2, off, 8);
            INS(e0, j0);
            INS(e1, j1);
            INS(e2, j2);
        }

        if (sub == 0) {
            // rare fallback: rings >= 2, same geometric bound (gmem)
            for (int rc = 2; rc < GRIDC; rc++) {
                float lb = (float)(CELL * (rc - 1));
                if (lb * lb > d2 + 0.5f) break;   // false while d2 = INF
                int Xlo = max(cx - rc, 0), Xhi = min(cx + rc, GRIDC - 1);
                int Ylo = max(cy - rc, 0), Yhi = min(cy + rc, GRIDC - 1);
                for (int y = Ylo; y <= Yhi; y++)
                    for (int x = Xlo; x <= Xhi; x++) {
                        if (y != cy - rc && y != cy + rc && x != cx - rc && x != cx + rc)
                            continue;
                        int c = b * NCELL + y * GRIDC + x;
                        int n = __ldg(&g_ccount[c]);
                        if (n > CAP) n = CAP;
                        const float4* cp = g_cellpts + (size_t)c * CAP;
                        for (int p = 0; p < n; p++) {
                            float4 P = cp[p];
                            float cross = __fmaf_rn(fy, P.y, __fmul_rn(fx, P.x));
                            float d = __fsub_rn(__fadd_rn(g2, P.z), __fadd_rn(cross, cross));
                            int idx = __float_as_int(P.w);
                            INS(d, idx);
                        }
                    }
            }
            sKnn[g * 3] = i0; sKnn[g * 3 + 1] = i1; sKnn[g * 3 + 2] = i2;
        }
    }
    __syncthreads();

    // ---- Phase 2: score (validated shfl z-path, 4 queries per warp) ----
    {
        int i_mine = lane & 15;
        int j_mine = lane >> 4;
        float w1a = w1[i_mine * 3 + 0];
        float w1b = w1[i_mine * 3 + 1];
        float w1c = w1[i_mine * 3 + 2];
        float b1r = b1[i_mine];
        float w2lo[16], w2hi[16];
        #pragma unroll
        for (int i = 0; i < 16; i++) {
            w2lo[i] = w2[lane * 16 + i];
            w2hi[i] = w2[(lane + 32) * 16 + i];
        }
        float b2lo = b2[lane], b2hi = b2[lane + 32];
        const float* uvb = uv + (size_t)b * 2 * NPTS;

        #pragma unroll
        for (int t = 0; t < 4; t++) {
            int g  = wid * 4 + t;          // query 0..15
            int px = cx * CELL + (g & 3);
            int py = cy * CELL + (g >> 2);
            float fx = (float)px;
            float fy = (float)py;

            int n0 = sKnn[g * 3];
            int n1 = sKnn[g * 3 + 1];
            int n2 = sKnn[g * 3 + 2];

            // feature gathers (coalesced per warp; independent of MLP chain)
            const float* f0 = g_f3t + ((size_t)(b * NPTS + n0)) * C_;
            const float* f1 = g_f3t + ((size_t)(b * NPTS + n1)) * C_;
            const float* f2 = g_f3t + ((size_t)(b * NPTS + n2)) * C_;
            float f0lo = f0[lane], f0hi = f0[lane + 32];
            float f1lo = f1[lane], f1hi = f1[lane + 32];
            float f2lo = f2[lane], f2hi = f2[lane + 32];

            // h for my (i_mine, j_mine) neighbor
            int   na = j_mine ? n1 : n0;
            float ua = uvb[na], va = uvb[NPTS + na];
            float oxa = ua - fx, oya = va - fy;
            float nrma = sqrtf(oxa * oxa + oya * oya);
            float ha = fmaf(w1c, nrma, fmaf(w1b, oya, w1a * oxa)) + b1r;
            ha = ha >= 0.f ? ha : LRELU_SLOPE * ha;
            // h for (i_mine, j=2)
            float ub = uvb[n2], vb = uvb[NPTS + n2];
            float oxb = ub - fx, oyb = vb - fy;
            float nrmb = sqrtf(oxb * oxb + oyb * oyb);
            float hb = fmaf(w1c, nrmb, fmaf(w1b, oyb, w1a * oxb)) + b1r;
            hb = hb >= 0.f ? hb : LRELU_SLOPE * hb;

            float zlo0 = b2lo, zlo1 = b2lo, zlo2 = b2lo;
            float zhi0 = b2hi, zhi1 = b2hi, zhi2 = b2hi;
            #pragma unroll
            for (int i = 0; i < 16; i++) {
                float h0 = __shfl_sync(0xffffffffu, ha, i);
                float h1 = __shfl_sync(0xffffffffu, ha, 16 + i);
                float h2 = __shfl_sync(0xffffffffu, hb, i);
                zlo0 = fmaf(w2lo[i], h0, zlo0);
                zlo1 = fmaf(w2lo[i], h1, zlo1);
                zlo2 = fmaf(w2lo[i], h2, zlo2);
                zhi0 = fmaf(w2hi[i], h0, zhi0);
                zhi1 = fmaf(w2hi[i], h1, zhi1);
                zhi2 = fmaf(w2hi[i], h2, zhi2);
            }
            float s0lo = 1.f / (1.f + __expf(-zlo0));
            float s1lo = 1.f / (1.f + __expf(-zlo1));
            float s2lo = 1.f / (1.f + __expf(-zlo2));
            float s0hi = 1.f / (1.f + __expf(-zhi0));
            float s1hi = 1.f / (1.f + __expf(-zhi1));
            float s2hi = 1.f / (1.f + __expf(-zhi2));

            float flo = fmaf(s2lo, f2lo, fmaf(s1lo, f1lo, s0lo * f0lo));
            float fhi = fmaf(s2hi, f2hi, fmaf(s1hi, f1hi, s0hi * f0hi));

            sF[g * 65 + lane]      = flo;
            sF[g * 65 + lane + 32] = fhi;
        }
    }
    __syncthreads();

    // ---- Phase 3: per-query 64x64 matvec (c ascending, validated order) ----
    {
        int qt = tid >> 3;            // 0..15
        int o0 = (tid & 7) * 8;       // 0..56
        float acc[8];
        #pragma unroll
        for (int oi = 0; oi < 8; oi++) acc[oi] = 0.f;

        #pragma unroll 8
        for (int c = 0; c < 64; c++) {
            float f = sF[qt * 65 + c];
            float4 wv0 = *(const float4*)&Wt[c * 64 + o0];
            float4 wv1 = *(const float4*)&Wt[c * 64 + o0 + 4];
            acc[0] = fmaf(wv0.x, f, acc[0]);
            acc[1] = fmaf(wv0.y, f, acc[1]);
            acc[2] = fmaf(wv0.z, f, acc[2]);
            acc[3] = fmaf(wv0.w, f, acc[3]);
            acc[4] = fmaf(wv1.x, f, acc[4]);
            acc[5] = fmaf(wv1.y, f, acc[5]);
            acc[6] = fmaf(wv1.z, f, acc[6]);
            acc[7] = fmaf(wv1.w, f, acc[7]);
        }
        #pragma unroll
        for (int oi = 0; oi < 8; oi++) {
            float v = acc[oi] + __ldg(&b_out[o0 + oi]);
            v = v >= 0.f ? v : LRELU_SLOPE * v;
            sOut[qt * 68 + o0 + oi] = v;
        }
    }
    __syncthreads();

    // ---- Phase 4: writeout, one float4 per (o, pixel row) ----
    #pragma unroll
    for (int k = 0; k < 2; k++) {
        int idx = tid + k * 128;      // 0..255
        int o   = idx >> 2;           // 0..63
        int pyi = idx & 3;            // pixel row within cell
        float4 v = make_float4(sOut[(pyi * 4 + 0) * 68 + o],
                               sOut[(pyi * 4 + 1) * 68 + o],
                               sOut[(pyi * 4 + 2) * 68 + o],
                               sOut[(pyi * 4 + 3) * 68 + o]);
        int q = (cy * CELL + pyi) * 64 + cx * CELL;
        *(float4*)(out + (((size_t)(b * 64 + o)) << 12) + q) = v;
    }

    // ---- last-finishing block resets g_ccount (all reads done block-wide) ----
    __syncthreads();
    if (tid == 0)
        sIsLast = (atomicAdd(&g_done, 1) == (int)gridDim.x - 1);
    __syncthreads();
    if (sIsLast) {
        for (int idx = tid; idx < BS * NCELL; idx += 128)
            g_ccount[idx] = 0;
        if (tid == 0) g_done = 0;
    }
}
#undef INS

// ---------------- launch ----------------
extern "C" void kernel_launch(void* const* d_in, const int* in_sizes, int n_in,
                              void* d_out, int out_size) {
    const float* uv      = (const float*)d_in[0];
    // d_in[1] = feat_2d: shape-only in reference, unused
    const float* feat_3d = (const float*)d_in[2];
    const float* w1      = (const float*)d_in[3];
    const float* b1      = (const float*)d_in[4];
    const float* w2      = (const float*)d_in[5];
    const float* b2      = (const float*)d_in[6];
    const float* w_out   = (const float*)d_in[7];
    const float* b_out   = (const float*)d_in[8];
    float* out = (float*)d_out;

    bin_transpose<<<64 + 1024, 256>>>(uv, feat_3d);
    fused_cell<<<BS * NCELL, 128>>>(uv, w1, b1, w2, b2, w_out, b_out, out);
}

// round 16
// speedup vs baseline: 1.8161x; 1.8161x over previous
#include <cuda_runtime.h>
#include <math.h>

// Fixed problem shapes
#define BS     4
#define C_     64
#define H_     64
#define W_     64
#define HW     4096     // H*W
#define NPTS   4096
#define M_TOT  (BS*HW)  // 16384

#define CELL   4
#define GRIDC  16       // 64/CELL
#define NCELL  (GRIDC*GRIDC)
#define CAP    64       // max points per cell (mean 16; +12 sigma unreachable)
#define CAND_CAP 640    // >= 9*CAP impossible; actual total ~144

#define LRELU_SLOPE 0.1f

// ---------------- device scratch (no allocations allowed) ----------------
__device__ float  g_f3t[BS * NPTS * C_];          // feat_3d transposed [b][n][c] (4 MB)
__device__ float4 g_cellpts[BS * NCELL * CAP];    // per-cell point arrays (1 MB)
__device__ int    g_ccount[BS * NCELL];           // zero at load; re-zeroed by K3 each call
__device__ int    g_knn[M_TOT * 3];               // knn indices

// ---------------- K1a: direct-scatter binning (64 blocks, 1 pt/thread) ----------------
__global__ void bin_points(const float* __restrict__ uv) {
    int b     = blockIdx.x >> 4;
    int slice = blockIdx.x & 15;
    int n     = slice * 256 + threadIdx.x;
    const float* uvb = uv + (size_t)b * 2 * NPTS;
    float u = uvb[n], v = uvb[NPTS + n];
    int cx = (int)(u * 0.25f);    // exact power-of-2 scale -> floor
    int cy = (int)(v * 0.25f);
    int c  = b * NCELL + cy * GRIDC + cx;
    int pos = atomicAdd(&g_ccount[c], 1);
    if (pos < CAP)
        g_cellpts[(size_t)c * CAP + pos] =
            make_float4(u, v,
                        __fadd_rn(__fmul_rn(u, u), __fmul_rn(v, v)),
                        __int_as_float(n));
}

// ---------------- K1b: transpose feat_3d (b,C,N) -> (b,N,C), float4 both ways ----------------
__global__ void transpose_f3(const float* __restrict__ f3) {
    __shared__ float tile[32][33];
    int tid = threadIdx.x;            // 128
    int b   = blockIdx.x >> 8;
    int rem = blockIdx.x & 255;
    int c0  = (rem >> 7) * 32;
    int n0  = (rem & 127) * 32;
    const float* src = f3 + ((size_t)(b * C_ + c0)) * NPTS + n0;
    #pragma unroll
    for (int k = 0; k < 2; k++) {
        int idx  = tid + k * 128;
        int row  = idx >> 3;          // c within tile
        int col4 = idx & 7;           // float4 slot along n
        float4 v = *(const float4*)(src + row * NPTS + col4 * 4);
        tile[row][col4 * 4 + 0] = v.x;
        tile[row][col4 * 4 + 1] = v.y;
        tile[row][col4 * 4 + 2] = v.z;
        tile[row][col4 * 4 + 3] = v.w;
    }
    __syncthreads();
    float* dst = g_f3t + ((size_t)(b * NPTS + n0)) * C_ + c0;
    #pragma unroll
    for (int k = 0; k < 2; k++) {
        int idx  = tid + k * 128;
        int n    = idx >> 3;          // n within tile
        int col4 = idx & 7;           // float4 slot along c
        float4 v = make_float4(tile[col4 * 4 + 0][n],
                               tile[col4 * 4 + 1][n],
                               tile[col4 * 4 + 2][n],
                               tile[col4 * 4 + 3][n]);
        *(float4*)(dst + n * C_ + col4 * 4) = v;
    }
}

// ---------------- K2: warp-cooperative KNN (validated) ----------------
// d rounding identical: cross = fma(fy, v, rn(fx*u)); d = rn(rn(g2+u2) - rn(2*cross))
// Selection: (d, idx) lexicographic -> order-independent, matches top_k ties.
#define INS(dv, iv)                                                     \
    if ((dv) < d2 || ((dv) == d2 && (iv) < i2)) {                       \
        if ((dv) < d1 || ((dv) == d1 && (iv) < i1)) {                   \
            d2 = d1; i2 = i1;                                           \
            if ((dv) < d0 || ((dv) == d0 && (iv) < i0)) {               \
                d1 = d0; i1 = i0; d0 = (dv); i0 = (iv);                 \
            } else { d1 = (dv); i1 = (iv); }                            \
        } else { d2 = (dv); i2 = (iv); }                                \
    }

__global__ void knn_search() {
    __shared__ float4 cand[CAND_CAP];

    int b    = blockIdx.x >> 8;
    int cell = blockIdx.x & 255;
    int cx = cell & (GRIDC - 1), cy = cell >> 4;
    int tid = threadIdx.x;            // 128

    int xlo = max(cx - 1, 0), xhi = min(cx + 1, GRIDC - 1);
    int ylo = max(cy - 1, 0), yhi = min(cy + 1, GRIDC - 1);
    int cbase[9], ccnt[9], coff[9], nc = 0, total = 0;
    for (int y = ylo; y <= yhi; y++)
        for (int x = xlo; x <= xhi; x++) {
            int c = b * NCELL + y * GRIDC + x;
            int n = __ldg(&g_ccount[c]);
            if (n > CAP) n = CAP;
            cbase[nc] = c * CAP; ccnt[nc] = n; coff[nc] = total;
            total += n; nc++;
        }

    for (int k = 0; k < nc; k++)
        for (int i = tid; i < ccnt[k]; i += 128)
            cand[coff[k] + i] = g_cellpts[(size_t)cbase[k] + i];
    __syncthreads();

    int g   = tid >> 3;               // 0..15
    int sub = tid & 7;
    int px = cx * CELL + (g & 3);
    int py = cy * CELL + (g >> 2);
    float fx = (float)px, fy = (float)py;
    float g2 = fx * fx + fy * fy;     // exact (small ints)

    float d0 = 3.4e38f, d1 = 3.4e38f, d2 = 3.4e38f;
    int   i0 = 0x7fffffff, i1 = 0x7fffffff, i2 = 0x7fffffff;

    for (int p = sub; p < total; p += 8) {
        float4 P = cand[p];
        float cross = __fmaf_rn(fy, P.y, __fmul_rn(fx, P.x));
        float d = __fsub_rn(__fadd_rn(g2, P.z), __fadd_rn(cross, cross));
        int idx = __float_as_int(P.w);
        INS(d, idx);
    }

    #pragma unroll
    for (int off = 4; off > 0; off >>= 1) {
        float e0 = __shfl_down_sync(0xffffffffu, d0, off, 8);
        int   j0 = __shfl_down_sync(0xffffffffu, i0, off, 8);
        float e1 = __shfl_down_sync(0xffffffffu, d1, off, 8);
        int   j1 = __shfl_down_sync(0xffffffffu, i1, off, 8);
        float e2 = __shfl_down_sync(0xffffffffu, d2, off, 8);
        int   j2 = __shfl_down_sync(0xffffffffu, i2, off, 8);
        INS(e0, j0);
        INS(e1, j1);
        INS(e2, j2);
    }

    if (sub == 0) {
        for (int rc = 2; rc < GRIDC; rc++) {
            float lb = (float)(CELL * (rc - 1));
            if (lb * lb > d2 + 0.5f) break;   // false while d2 = INF
            int Xlo = max(cx - rc, 0), Xhi = min(cx + rc, GRIDC - 1);
            int Ylo = max(cy - rc, 0), Yhi = min(cy + rc, GRIDC - 1);
            for (int y = Ylo; y <= Yhi; y++)
                for (int x = Xlo; x <= Xhi; x++) {
                    if (y != cy - rc && y != cy + rc && x != cx - rc && x != cx + rc)
                        continue;
                    int c = b * NCELL + y * GRIDC + x;
                    int n = __ldg(&g_ccount[c]);
                    if (n > CAP) n = CAP;
                    const float4* cp = g_cellpts + (size_t)c * CAP;
                    for (int p = 0; p < n; p++) {
                        float4 P = cp[p];
                        float cross = __fmaf_rn(fy, P.y, __fmul_rn(fx, P.x));
                        float d = __fsub_rn(__fadd_rn(g2, P.z), __fadd_rn(cross, cross));
                        int idx = __float_as_int(P.w);
                        INS(d, idx);
                    }
                }
        }
        int m = b * HW + py * 64 + px;
        g_knn[m * 3] = i0; g_knn[m * 3 + 1] = i1; g_knn[m * 3 + 2] = i2;
    }
}
#undef INS

// ---------------- K3: fused score MLP + gather + out GEMM (m-tile 64, validated) ----------------
__global__ void fused_score_gemm(const float* __restrict__ uv,
                                 const float* __restrict__ w1, const float* __restrict__ b1,
                                 const float* __restrict__ w2, const float* __restrict__ b2,
                                 const float* __restrict__ w_out,
                                 const float* __restrict__ b_out,
                                 float* __restrict__ out) {
    __shared__ float Wt[64 * 64];     // [c][o] for LDS.128 reads
    __shared__ float Fs[64 * 64];     // swizzled: row r, col (c+r)&63

    int tid  = threadIdx.x;
    int lane = tid & 31;
    int wid  = tid >> 5;              // 8 warps
    int m0   = blockIdx.x * 64;

    // reset cell counts for next call (counts already consumed by K2)
    if (blockIdx.x == 0) {
        #pragma unroll
        for (int k = 0; k < (BS * NCELL) / 256; k++)
            g_ccount[tid + k * 256] = 0;
    }

    for (int idx = tid; idx < 4096; idx += 256) {
        int o = idx >> 6, c = idx & 63;
        Wt[c * 64 + o] = w_out[idx];
    }

    // ---- phase 1: score (validated shfl z-path, QPW=8) ----
    int i_mine = lane & 15;
    int j_mine = lane >> 4;
    float w1a = w1[i_mine * 3 + 0];
    float w1b = w1[i_mine * 3 + 1];
    float w1c = w1[i_mine * 3 + 2];
    float b1r = b1[i_mine];
    float w2lo[16], w2hi[16];
    #pragma unroll
    for (int i = 0; i < 16; i++) {
        w2lo[i] = w2[lane * 16 + i];
        w2hi[i] = w2[(lane + 32) * 16 + i];
    }
    float b2lo = b2[lane], b2hi = b2[lane + 32];

    int base_m = m0 + wid * 8;
    #pragma unroll
    for (int t = 0; t < 8; t++) {
        int m = base_m + t;                // 0..16383
        int b = m >> 12;
        int q = m & 4095;
        float fx = (float)(q & 63);
        float fy = (float)(q >> 6);

        int n0 = __ldg(&g_knn[m * 3]);
        int n1 = __ldg(&g_knn[m * 3 + 1]);
        int n2 = __ldg(&g_knn[m * 3 + 2]);
        const float* uvb = uv + (size_t)b * 2 * NPTS;

        const float* f0 = g_f3t + ((size_t)(b * NPTS + n0)) * C_;
        const float* f1 = g_f3t + ((size_t)(b * NPTS + n1)) * C_;
        const float* f2 = g_f3t + ((size_t)(b * NPTS + n2)) * C_;
        float f0lo = f0[lane], f0hi = f0[lane + 32];
        float f1lo = f1[lane], f1hi = f1[lane + 32];
        float f2lo = f2[lane], f2hi = f2[lane + 32];

        int   na = j_mine ? n1 : n0;
        float ua = uvb[na], va = uvb[NPTS + na];
        float oxa = ua - fx, oya = va - fy;
        float nrma = sqrtf(oxa * oxa + oya * oya);
        float ha = fmaf(w1c, nrma, fmaf(w1b, oya, w1a * oxa)) + b1r;
        ha = ha >= 0.f ? ha : LRELU_SLOPE * ha;
        float ub = uvb[n2], vb = uvb[NPTS + n2];
        float oxb = ub - fx, oyb = vb - fy;
        float nrmb = sqrtf(oxb * oxb + oyb * oyb);
        float hb = fmaf(w1c, nrmb, fmaf(w1b, oyb, w1a * oxb)) + b1r;
        hb = hb >= 0.f ? hb : LRELU_SLOPE * hb;

        float zlo0 = b2lo, zlo1 = b2lo, zlo2 = b2lo;
        float zhi0 = b2hi, zhi1 = b2hi, zhi2 = b2hi;
        #pragma unroll
        for (int i = 0; i < 16; i++) {
            float h0 = __shfl_sync(0xffffffffu, ha, i);
            float h1 = __shfl_sync(0xffffffffu, ha, 16 + i);
            float h2 = __shfl_sync(0xffffffffu, hb, i);
            zlo0 = fmaf(w2lo[i], h0, zlo0);
            zlo1 = fmaf(w2lo[i], h1, zlo1);
            zlo2 = fmaf(w2lo[i], h2, zlo2);
            zhi0 = fmaf(w2hi[i], h0, zhi0);
            zhi1 = fmaf(w2hi[i], h1, zhi1);
            zhi2 = fmaf(w2hi[i], h2, zhi2);
        }
        float s0lo = 1.f / (1.f + __expf(-zlo0));
        float s1lo = 1.f / (1.f + __expf(-zlo1));
        float s2lo = 1.f / (1.f + __expf(-zlo2));
        float s0hi = 1.f / (1.f + __expf(-zhi0));
        float s1hi = 1.f / (1.f + __expf(-zhi1));
        float s2hi = 1.f / (1.f + __expf(-zhi2));

        float flo = fmaf(s2lo, f2lo, fmaf(s1lo, f1lo, s0lo * f0lo));
        float fhi = fmaf(s2hi, f2hi, fmaf(s1hi, f1hi, s0hi * f0hi));

        int r = wid * 8 + t;
        Fs[r * 64 + ((lane + r) & 63)]      = flo;
        Fs[r * 64 + ((lane + 32 + r) & 63)] = fhi;
    }
    __syncthreads();

    // ---- phase 2: GEMM (64 rows x 64 out-channels) ----
    int mi = lane;
    int og = wid;
    float acc[2][8];
    #pragma unroll
    for (int j = 0; j < 2; j++)
        #pragma unroll
        for (int oi = 0; oi < 8; oi++) acc[j][oi] = 0.f;

    #pragma unroll 8
    for (int c = 0; c < 64; c++) {
        float4 wv0 = *(const float4*)&Wt[c * 64 + og * 8];
        float4 wv1 = *(const float4*)&Wt[c * 64 + og * 8 + 4];
        #pragma unroll
        for (int j = 0; j < 2; j++) {
            int r = mi + 32 * j;
            float f = Fs[r * 64 + ((c + r) & 63)];
            acc[j][0] = fmaf(wv0.x, f, acc[j][0]);
            acc[j][1] = fmaf(wv0.y, f, acc[j][1]);
            acc[j][2] = fmaf(wv0.z, f, acc[j][2]);
            acc[j][3] = fmaf(wv0.w, f, acc[j][3]);
            acc[j][4] = fmaf(wv1.x, f, acc[j][4]);
            acc[j][5] = fmaf(wv1.y, f, acc[j][5]);
            acc[j][6] = fmaf(wv1.z, f, acc[j][6]);
            acc[j][7] = fmaf(wv1.w, f, acc[j][7]);
        }
    }
    #pragma unroll
    for (int oi = 0; oi < 8; oi++) {
        int o = og * 8 + oi;
        float bo = __ldg(&b_out[o]);
        #pragma unroll
        for (int j = 0; j < 2; j++) {
            int m = m0 + mi + 32 * j;
            int b = m >> 12;
            int q = m & 4095;
            float v = acc[j][oi] + bo;
            v = v >= 0.f ? v : LRELU_SLOPE * v;
            out[((size_t)(b * 64 + o) << 12) + q] = v;
        }
    }
}

// ---------------- launch: fork/join graph ----------------
// stream0: bin -> transpose -> [wait knn] -> fused
// s2:      [wait bin] -> knn
static cudaStream_t g_s2 = nullptr;
static cudaEvent_t  g_evBin = nullptr, g_evKnn = nullptr;

extern "C" void kernel_launch(void* const* d_in, const int* in_sizes, int n_in,
                              void* d_out, int out_size) {
    const float* uv      = (const float*)d_in[0];
    // d_in[1] = feat_2d: shape-only in reference, unused
    const float* feat_3d = (const float*)d_in[2];
    const float* w1      = (const float*)d_in[3];
    const float* b1      = (const float*)d_in[4];
    const float* w2      = (const float*)d_in[5];
    const float* b2      = (const float*)d_in[6];
    const float* w_out   = (const float*)d_in[7];
    const float* b_out   = (const float*)d_in[8];
    float* out = (float*)d_out;

    if (!g_s2) {
        cudaStreamCreateWithFlags(&g_s2, cudaStreamNonBlocking);
        cudaEventCreateWithFlags(&g_evBin, cudaEventDisableTiming);
        cudaEventCreateWithFlags(&g_evKnn, cudaEventDisableTiming);
    }

    bin_points<<<64, 256>>>(uv);
    cudaEventRecord(g_evBin, 0);
    cudaStreamWaitEvent(g_s2, g_evBin, 0);
    knn_search<<<BS * NCELL, 128, 0, g_s2>>>();
    cudaEventRecord(g_evKnn, g_s2);

    transpose_f3<<<BS * 256, 128>>>(feat_3d);

    cudaStreamWaitEvent(0, g_evKnn, 0);
    fused_score_gemm<<<M_TOT / 64, 256>>>(uv, w1, b1, w2, b2, w_out, b_out, out);
}